// round 11
// baseline (speedup 1.0000x reference)
#include <cuda_runtime.h>
#include <cuda_bf16.h>
#include <math.h>
#include <stdint.h>

// Problem dims
#define Bsz 256
#define Ssz 128
#define Tsz 64
#define Isz 63
#define Hsz 1024
#define G3  (3*Hsz)   // 3072

// Scratch (device globals — no allocations allowed)
__device__ float g_GI[(size_t)Bsz * Ssz * G3];      // encoder gi_all (B*S, 3H)
__device__ float g_G2[(size_t)Bsz * Tsz * G3];      // decoder gi     (B*T, 3H)
__device__ float g_GH[(size_t)Bsz * G3];            // decoder gh     (B, 3H)
__device__ float g_states[(size_t)Bsz * Tsz * Hsz]; // decoder states (B*T, H)
__device__ float g_hbuf[2][(size_t)Bsz * Hsz];      // hidden fp32, double buffered
__device__ signed char g_h1[2][(size_t)Bsz * Hsz];  // h digit 1 (s8)
__device__ signed char g_h2[2][(size_t)Bsz * Hsz];  // h digit 2 (s8)
__device__ signed char g_w1[(size_t)G3 * Hsz];      // Whh digit 1 (s8, scale 0.25)
__device__ signed char g_w2[(size_t)G3 * Hsz];      // Whh digit 2 (s8)

// scale constants: h = (x1 + x2/127)/127, w = 0.25*(w1 + w2/127)/127
// gh = C1*sum(x1w1) + C2*(sum(x1w2)+sum(x2w1))
#define WSCALE 0.25f
#define C1 (WSCALE / (127.0f * 127.0f))
#define C2 (C1 / 127.0f)

// ---------------------------------------------------------------------------
__device__ __forceinline__ uint32_t smem_u32(const void* p) {
    uint32_t a;
    asm("{ .reg .u64 t; cvta.to.shared.u64 t, %1; cvt.u32.u64 %0, t; }"
        : "=r"(a) : "l"(p));
    return a;
}
__device__ __forceinline__ void cpasync16(uint32_t dst, const void* src) {
    asm volatile("cp.async.cg.shared.global [%0], [%1], 16;"
                 :: "r"(dst), "l"(src) : "memory");
}
#define CP_COMMIT() asm volatile("cp.async.commit_group;" ::: "memory")
#define CP_WAIT(n)  asm volatile("cp.async.wait_group %0;" :: "n"(n) : "memory")

__device__ __forceinline__ void ldsm4(uint32_t* r, uint32_t addr) {
    asm volatile("ldmatrix.sync.aligned.m8n8.x4.shared.b16 {%0,%1,%2,%3}, [%4];"
                 : "=r"(r[0]), "=r"(r[1]), "=r"(r[2]), "=r"(r[3]) : "r"(addr));
}
__device__ __forceinline__ void ldsm2(uint32_t* r, uint32_t addr) {
    asm volatile("ldmatrix.sync.aligned.m8n8.x2.shared.b16 {%0,%1}, [%2];"
                 : "=r"(r[0]), "=r"(r[1]) : "r"(addr));
}
// int8 MMA: m16n8k32, s32 accumulate
__device__ __forceinline__ void mma_s8(int32_t* d, const uint32_t* a, const uint32_t* b) {
    asm volatile("mma.sync.aligned.m16n8k32.row.col.s32.s8.s8.s32 "
                 "{%0,%1,%2,%3}, {%4,%5,%6,%7}, {%8,%9}, {%0,%1,%2,%3};"
                 : "+r"(d[0]), "+r"(d[1]), "+r"(d[2]), "+r"(d[3])
                 : "r"(a[0]), "r"(a[1]), "r"(a[2]), "r"(a[3]),
                   "r"(b[0]), "r"(b[1]));
}

__device__ __forceinline__ float sigf(float x) { return 1.f / (1.f + expf(-x)); }

// ---------------------------------------------------------------------------
// int8 dual-digit warp-MMA fused GRU step.
// CTA tile M=32, N=48 (16 j x 3 gates), K=1024 in 32 chunks of 32.
// Grid (64 j, 8 m) = 512 CTAs; 128 threads = 4 warps as 2m x 2n (warp 16x24).
// Per chunk per warp: 2 ldsm4 (A digits) + 6 ldsm2 (B digits) + 9 mma.k32.
// accM = x1*w1 (s32 exact); accC = x1*w2 + x2*w1 (s32 exact); x2*w2 dropped.
// 4-stage cp.async pipeline (stage 7.68KB). Rows padded to 48B (conflict-free).
// ---------------------------------------------------------------------------
#define KC 32                  // k-bytes per chunk (s8)
#define NCH (Hsz / KC)         // 32
#define NSTAGE 4
#define AROWB 48
#define OFF_A1 0u
#define OFF_A2 1536u           // 32*48
#define OFF_B1 3072u
#define OFF_B2 5376u           // +48*48
#define STAGE_B 7680u
#define DSMEM (NSTAGE * 7680)  // 30720 (<48KB, no attribute needed)
#define GH_STR 52

__global__ __launch_bounds__(128) void gru_step_i8(
    const signed char* __restrict__ h1in,
    const signed char* __restrict__ h2in,
    const float* __restrict__ hprev,
    float*       __restrict__ hout,
    signed char* __restrict__ h1out,
    signed char* __restrict__ h2out,
    const float* __restrict__ bhh,
    int t)
{
    extern __shared__ __align__(16) char dsmem[];
    const uint32_t sb0 = smem_u32(dsmem);

    const int tid  = threadIdx.x;
    const int wid  = tid >> 5;
    const int lane = tid & 31;
    const int j0   = blockIdx.x << 4;     // 16 j per CTA
    const int m0   = blockIdx.y << 5;     // 32 batch per CTA

    const int wm  = wid & 1;              // 2 m-warps (16 rows each)
    const int wn  = wid >> 1;             // 2 n-warps (24 cols each)
    const int m0w = wm << 4;
    const int n0w = wn * 24;

    // ---- epilogue operand prefetch (DRAM latency hidden behind mainloop)
    float pgr[4], pgz[4], pgn[4], php[4];
#pragma unroll
    for (int it = 0; it < 4; it++) {
        const int flat = tid + (it << 7);
        const int m  = flat >> 4;
        const int jj = flat & 15;
        const int gm = m0 + m;
        const float* gi = g_GI + ((size_t)gm * Ssz + t) * G3 + j0 + jj;
        pgr[it] = gi[0];
        pgz[it] = gi[Hsz];
        pgn[it] = gi[2 * Hsz];
        php[it] = hprev[(size_t)gm * Hsz + j0 + jj];
    }

    // ldmatrix per-lane address components (byte offsets)
    const int arow = (((lane >> 3) & 1) << 3) + (lane & 7);  // A row in m16
    const int akof = (lane >> 4) << 4;                       // A k byte (0/16)
    const int brow = lane & 7;                               // B row in n8
    const int bkof = ((lane >> 3) & 1) << 4;                 // B k byte (0/16)

    int32_t accM[3][4], accC[3][4];
#pragma unroll
    for (int j = 0; j < 3; j++)
#pragma unroll
        for (int e = 0; e < 4; e++) { accM[j][e] = 0; accC[j][e] = 0; }

    // ---- chunk loader (cp.async): A 32x32B (2 digits), B 48x32B (2 digits)
    auto load_chunk = [&](int c, int s) {
        const uint32_t sb = sb0 + (uint32_t)s * STAGE_B;
        const int k0 = c * KC;   // byte offset in K
        if (tid < 64) {
            const int row = tid >> 1, seg = tid & 1;    // 32 rows x 2 segs
            const size_t src = (size_t)(m0 + row) * Hsz + k0 + seg * 16;
            const uint32_t dst = sb + row * AROWB + seg * 16;
            cpasync16(dst + OFF_A1, h1in + src);
            cpasync16(dst + OFF_A2, h2in + src);
        }
        if (tid < 96) {
            const int row = tid >> 1, seg = tid & 1;    // 48 rows x 2 segs
            const int gate = row >> 4, jj = row & 15;
            const size_t src = ((size_t)gate * Hsz + j0 + jj) * Hsz + k0 + seg * 16;
            const uint32_t dst = sb + row * AROWB + seg * 16;
            cpasync16(dst + OFF_B1, g_w1 + src);
            cpasync16(dst + OFF_B2, g_w2 + src);
        }
        CP_COMMIT();
    };

    // prologue: 3 chunks in flight
#pragma unroll
    for (int c = 0; c < NSTAGE - 1; c++) load_chunk(c, c);

    for (int c = 0; c < NCH; c++) {
        const int s = c & (NSTAGE - 1);
        const int rem = NCH - 1 - c;
        if      (rem >= 2) CP_WAIT(2);
        else if (rem == 1) CP_WAIT(1);
        else               CP_WAIT(0);
        __syncthreads();   // publishes chunk c; proves compute c-1 done

        if (c + NSTAGE - 1 < NCH)
            load_chunk(c + NSTAGE - 1, (c + NSTAGE - 1) & (NSTAGE - 1));

        const uint32_t sb = sb0 + (uint32_t)s * STAGE_B;
        const uint32_t a1 = sb + OFF_A1 + (m0w + arow) * AROWB + akof;
        const uint32_t a2 = sb + OFF_A2 + (m0w + arow) * AROWB + akof;
        const uint32_t b1 = sb + OFF_B1 + (n0w + brow) * AROWB + bkof;
        const uint32_t b2 = sb + OFF_B2 + (n0w + brow) * AROWB + bkof;

        uint32_t A1[4], A2[4], B1[3][2], B2[3][2];
        ldsm4(A1, a1);
        ldsm4(A2, a2);
#pragma unroll
        for (int j = 0; j < 3; j++) {
            ldsm2(B1[j], b1 + j * (8 * AROWB));
            ldsm2(B2[j], b2 + j * (8 * AROWB));
        }
#pragma unroll
        for (int j = 0; j < 3; j++) {
            mma_s8(accM[j], A1, B1[j]);
            mma_s8(accC[j], A1, B2[j]);
            mma_s8(accC[j], A2, B1[j]);
        }
        // no trailing barrier: next iteration's top barrier protects stage reuse
    }
    __syncthreads();   // all compute done before reusing smem for epilogue

    // ---- convert + dump gh (fp32) to smem, padded stride
    float* ghs = reinterpret_cast<float*>(dsmem);
    const int crow = m0w + (lane >> 2);
    const int ccol = n0w + ((lane & 3) << 1);
#pragma unroll
    for (int j = 0; j < 3; j++) {
        const int col = ccol + (j << 3);
        *reinterpret_cast<float2*>(&ghs[crow * GH_STR + col]) =
            make_float2(C1 * (float)accM[j][0] + C2 * (float)accC[j][0],
                        C1 * (float)accM[j][1] + C2 * (float)accC[j][1]);
        *reinterpret_cast<float2*>(&ghs[(crow + 8) * GH_STR + col]) =
            make_float2(C1 * (float)accM[j][2] + C2 * (float)accC[j][2],
                        C1 * (float)accM[j][3] + C2 * (float)accC[j][3]);
    }
    __syncthreads();

    // ---- GRU gates: 512 (m, jj) pairs, 4 per thread (operands prefetched)
#pragma unroll
    for (int it = 0; it < 4; it++) {
        const int flat = tid + (it << 7);
        const int m  = flat >> 4;
        const int jj = flat & 15;
        const int j  = j0 + jj;
        const int gm = m0 + m;

        const float ghr = ghs[m * GH_STR + jj]       + bhh[j];
        const float ghz = ghs[m * GH_STR + 16 + jj]  + bhh[Hsz + j];
        const float ghn = ghs[m * GH_STR + 32 + jj]  + bhh[2 * Hsz + j];

        const float r  = sigf(pgr[it] + ghr);
        const float z  = sigf(pgz[it] + ghz);
        const float nn = tanhf(pgn[it] + r * ghn);
        const float hv = (1.f - z) * nn + z * php[it];   // |hv| <= 1

        hout[(size_t)gm * Hsz + j] = hv;
        // dual-digit s8 quantization of h
        const float q1 = rintf(hv * 127.f);              // in [-127,127]
        const float q2 = rintf((hv * 127.f - q1) * 127.f);
        h1out[(size_t)gm * Hsz + j] = (signed char)(int)q1;
        h2out[(size_t)gm * Hsz + j] = (signed char)(int)q2;
    }
}

// ---------------------------------------------------------------------------
// Quantize Whh into dual s8 digits (scale 0.25), once per run
__global__ void quant_whh_kernel(const float* __restrict__ Whh)
{
    const size_t idx = (size_t)blockIdx.x * blockDim.x + threadIdx.x;
    const float w = Whh[idx] * (1.0f / WSCALE);    // |w/0.25| < 1 (10+ sigma)
    float q1 = rintf(w * 127.f);
    q1 = fminf(fmaxf(q1, -127.f), 127.f);
    float q2 = rintf((w * 127.f - q1) * 127.f);
    q2 = fminf(fmaxf(q2, -127.f), 127.f);
    g_w1[idx] = (signed char)(int)q1;
    g_w2[idx] = (signed char)(int)q2;
}

__global__ void zero_h_kernel()
{
    const int idx = blockIdx.x * blockDim.x + threadIdx.x;
    g_hbuf[0][idx] = 0.f;
    g_h1[0][idx] = 0;
    g_h2[0][idx] = 0;
}

// ---------------------------------------------------------------------------
// Generic tiled SGEMM with bias (parallel GEMMs: GI, G2, GH, projector)
// ---------------------------------------------------------------------------
__global__ __launch_bounds__(256) void sgemm_bias(
    const float* __restrict__ A, int lda,
    const float* __restrict__ W,
    const float* __restrict__ bias,
    float* __restrict__ C,
    int N, int K)
{
    __shared__ float As[16][64];
    __shared__ float Bsh[16][64];

    const int tid  = threadIdx.x;
    const int tx   = tid & 15;
    const int ty   = tid >> 4;
    const int row0 = blockIdx.y << 6;
    const int col0 = blockIdx.x << 6;

    const int lm = tid >> 2;
    const int lk = (tid & 3) << 2;

    float acc[4][4] = {};

    for (int k0 = 0; k0 < K; k0 += 16) {
#pragma unroll
        for (int c = 0; c < 4; c++) {
            const int k = k0 + lk + c;
            As[lk + c][lm] = (k < K) ? A[(size_t)(row0 + lm) * lda + k] : 0.f;
            const int n = col0 + lm;
            Bsh[lk + c][lm] = (k < K && n < N) ? W[(size_t)n * K + k] : 0.f;
        }
        __syncthreads();

#pragma unroll
        for (int k = 0; k < 16; k++) {
            const float4 av = *reinterpret_cast<const float4*>(&As[k][ty << 2]);
            const float4 bv = *reinterpret_cast<const float4*>(&Bsh[k][tx << 2]);
            const float a[4] = {av.x, av.y, av.z, av.w};
            const float b[4] = {bv.x, bv.y, bv.z, bv.w};
#pragma unroll
            for (int i = 0; i < 4; i++)
#pragma unroll
                for (int j = 0; j < 4; j++)
                    acc[i][j] = fmaf(a[i], b[j], acc[i][j]);
        }
        __syncthreads();
    }

#pragma unroll
    for (int i = 0; i < 4; i++) {
        const int m = row0 + (ty << 2) + i;
#pragma unroll
        for (int j = 0; j < 4; j++) {
            const int n = col0 + (tx << 2) + j;
            if (n < N)
                C[(size_t)m * N + n] = acc[i][j] + bias[n];
        }
    }
}

// Decoder gates: every timestep uses the same enc_h and the same gh row.
__global__ void gates_dec_kernel(const float* __restrict__ hfin)
{
    const size_t idx = (size_t)blockIdx.x * blockDim.x + threadIdx.x;
    const int j  = (int)(idx & (Hsz - 1));
    const int bt = (int)(idx >> 10);
    const int b  = bt >> 6;
    const float* gi = g_G2 + (size_t)bt * G3;
    const float* gh = g_GH + (size_t)b * G3;

    const float r  = sigf(gi[j]          + gh[j]);
    const float z  = sigf(gi[Hsz + j]    + gh[Hsz + j]);
    const float nn = tanhf(gi[2*Hsz + j] + r * gh[2*Hsz + j]);
    const float hp = hfin[(size_t)b * Hsz + j];
    g_states[idx] = (1.f - z) * nn + z * hp;
}

// ---------------------------------------------------------------------------
extern "C" void kernel_launch(void* const* d_in, const int* in_sizes, int n_in,
                              void* d_out, int out_size)
{
    const float* enc_in  = (const float*)d_in[0];
    const float* dec_in  = (const float*)d_in[1];
    const float* enc_Wih = (const float*)d_in[2];
    const float* enc_Whh = (const float*)d_in[3];
    const float* enc_bih = (const float*)d_in[4];
    const float* enc_bhh = (const float*)d_in[5];
    const float* dec_Wih = (const float*)d_in[6];
    const float* dec_Whh = (const float*)d_in[7];
    const float* dec_bih = (const float*)d_in[8];
    const float* dec_bhh = (const float*)d_in[9];
    const float* proj_W  = (const float*)d_in[10];
    const float* proj_b  = (const float*)d_in[11];
    float* out = (float*)d_out;

    float *GI, *G2, *GH, *states, *hbuf;
    signed char *h1, *h2;
    cudaGetSymbolAddress((void**)&GI,     g_GI);
    cudaGetSymbolAddress((void**)&G2,     g_G2);
    cudaGetSymbolAddress((void**)&GH,     g_GH);
    cudaGetSymbolAddress((void**)&states, g_states);
    cudaGetSymbolAddress((void**)&hbuf,   g_hbuf);
    cudaGetSymbolAddress((void**)&h1,     g_h1);
    cudaGetSymbolAddress((void**)&h2,     g_h2);
    float* hf0 = hbuf;
    float* hf1 = hbuf + (size_t)Bsz * Hsz;
    signed char* h1a = h1; signed char* h1b = h1 + (size_t)Bsz * Hsz;
    signed char* h2a = h2; signed char* h2b = h2 + (size_t)Bsz * Hsz;

    const dim3 blk256(256);

    zero_h_kernel<<<(Bsz * Hsz) / 256, blk256>>>();
    quant_whh_kernel<<<(int)(((size_t)G3 * Hsz) / 256), blk256>>>(enc_Whh);

    // Encoder input gates for ALL timesteps
    sgemm_bias<<<dim3(G3 / 64, (Bsz * Ssz) / 64), blk256>>>(
        enc_in, Isz, enc_Wih, enc_bih, GI, G3, Isz);

    // Encoder recurrence: 128 sequential int8 warp-MMA steps
    for (int t = 0; t < Ssz; t++) {
        const int s = t & 1;
        gru_step_i8<<<dim3(Hsz / 16, Bsz / 32), 128, DSMEM>>>(
            s ? h1b : h1a, s ? h2b : h2a, s ? hf1 : hf0,
            s ? hf0 : hf1, s ? h1a : h1b, s ? h2a : h2b,
            enc_bhh, t);
    }
    float* enc_h = hf0;   // 128 steps (even) -> buffer 0

    // Decoder hidden-side gates (shared by all T timesteps)
    sgemm_bias<<<dim3(G3 / 64, Bsz / 64), blk256>>>(
        enc_h, Hsz, dec_Whh, dec_bhh, GH, G3, Hsz);

    // Decoder input-side gates for all timesteps
    sgemm_bias<<<dim3(G3 / 64, (Bsz * Tsz) / 64), blk256>>>(
        dec_in, Isz, dec_Wih, dec_bih, G2, G3, Isz);

    // Decoder gates -> states (B*T, H)
    gates_dec_kernel<<<(int)(((size_t)Bsz * Tsz * Hsz) / 256), blk256>>>(enc_h);

    // Projector: out (B*T, I) = states @ proj_W^T + proj_b
    sgemm_bias<<<dim3((Isz + 63) / 64, (Bsz * Tsz) / 64), blk256>>>(
        states, Hsz, proj_W, proj_b, out, Isz, Hsz);
}

// round 12
// speedup vs baseline: 1.8004x; 1.8004x over previous
#include <cuda_runtime.h>
#include <cuda_fp16.h>
#include <math.h>
#include <stdint.h>

// Problem dims
#define Bsz 256
#define Ssz 128
#define Tsz 64
#define Isz 63
#define Hsz 1024
#define G3  (3*Hsz)   // 3072

// Scratch (device globals — no allocations allowed)
__device__ float g_GI[(size_t)Bsz * Ssz * G3];      // encoder gi_all (B*S, 3H)
__device__ float g_G2[(size_t)Bsz * Tsz * G3];      // decoder gi     (B*T, 3H)
__device__ float g_GH[(size_t)Bsz * G3];            // decoder gh     (B, 3H)
__device__ float g_states[(size_t)Bsz * Tsz * Hsz]; // decoder states (B*T, H)
__device__ float g_hbuf[2][(size_t)Bsz * Hsz];      // hidden fp32, double buffered
__device__ __half g_hh[2][(size_t)Bsz * Hsz];       // h split hi (fp16)
__device__ __half g_hl[2][(size_t)Bsz * Hsz];       // h split lo (fp16)
__device__ __half g_wq[(size_t)G3 * Hsz];           // Whh quantized fp16

// ---------------------------------------------------------------------------
__device__ __forceinline__ uint32_t smem_u32(const void* p) {
    uint32_t a;
    asm("{ .reg .u64 t; cvta.to.shared.u64 t, %1; cvt.u32.u64 %0, t; }"
        : "=r"(a) : "l"(p));
    return a;
}
__device__ __forceinline__ void cpasync16(uint32_t dst, const void* src) {
    asm volatile("cp.async.cg.shared.global [%0], [%1], 16;"
                 :: "r"(dst), "l"(src) : "memory");
}
#define CP_COMMIT() asm volatile("cp.async.commit_group;" ::: "memory")
#define CP_WAIT(n)  asm volatile("cp.async.wait_group %0;" :: "n"(n) : "memory")

__device__ __forceinline__ void ldsm4(uint32_t* r, uint32_t addr) {
    asm volatile("ldmatrix.sync.aligned.m8n8.x4.shared.b16 {%0,%1,%2,%3}, [%4];"
                 : "=r"(r[0]), "=r"(r[1]), "=r"(r[2]), "=r"(r[3]) : "r"(addr));
}
__device__ __forceinline__ void ldsm2(uint32_t* r, uint32_t addr) {
    asm volatile("ldmatrix.sync.aligned.m8n8.x2.shared.b16 {%0,%1}, [%2];"
                 : "=r"(r[0]), "=r"(r[1]) : "r"(addr));
}
__device__ __forceinline__ void mma_f16(float* d, const uint32_t* a, const uint32_t* b) {
    asm volatile("mma.sync.aligned.m16n8k16.row.col.f32.f16.f16.f32 "
                 "{%0,%1,%2,%3}, {%4,%5,%6,%7}, {%8,%9}, {%0,%1,%2,%3};"
                 : "+f"(d[0]), "+f"(d[1]), "+f"(d[2]), "+f"(d[3])
                 : "r"(a[0]), "r"(a[1]), "r"(a[2]), "r"(a[3]),
                   "r"(b[0]), "r"(b[1]));
}

__device__ __forceinline__ float sigf(float x) { return 1.f / (1.f + expf(-x)); }

// ---------------------------------------------------------------------------
// fp16 2-MMA warp-MMA fused GRU step.
// Split only h: gh = Ah*B + Al*B  (Ah=fp16(h), Al=fp16(h-Ah), B=fp16(w)).
// CTA tile M=32, N=48 (16 j x 3 gates), K=1024 in 32 chunks of 32.
// Grid (64 j, 8 m) = 512 CTAs; 128 threads = 4 warps as 2m x 2n (warp 16x24).
// Per chunk per warp: 2 ldsm4 (A hi/lo) + 3 ldsm2 (B) + 12 mma (was 18).
// 4-stage cp.async pipeline (stage 8.96KB). Rows padded to 80B (conflict-free).
// ---------------------------------------------------------------------------
#define KC 32                  // k-elements per chunk
#define NCH (Hsz / KC)         // 32
#define NSTAGE 4
#define AROWB 80               // 32 fp16 = 64B + 16B pad
#define OFF_AH 0u
#define OFF_AL 2560u           // 32*80
#define OFF_B  5120u
#define STAGE_B 8960u          // + 48*80
#define DSMEM (NSTAGE * 8960)  // 35840 (<48KB)
#define GH_STR 52

__global__ __launch_bounds__(128) void gru_step_f16(
    const __half* __restrict__ hhin,
    const __half* __restrict__ hlin,
    const float* __restrict__ hprev,
    float*       __restrict__ hout,
    __half* __restrict__ hhout,
    __half* __restrict__ hlout,
    const float* __restrict__ bhh,
    int t)
{
    extern __shared__ __align__(16) char dsmem[];
    const uint32_t sb0 = smem_u32(dsmem);

    const int tid  = threadIdx.x;
    const int wid  = tid >> 5;
    const int lane = tid & 31;
    const int j0   = blockIdx.x << 4;     // 16 j per CTA
    const int m0   = blockIdx.y << 5;     // 32 batch per CTA

    const int wm  = wid & 1;              // 2 m-warps (16 rows each)
    const int wn  = wid >> 1;             // 2 n-warps (24 cols each)
    const int m0w = wm << 4;
    const int n0w = wn * 24;

    // ---- epilogue operand prefetch (DRAM latency hidden behind mainloop)
    float pgr[4], pgz[4], pgn[4], php[4];
#pragma unroll
    for (int it = 0; it < 4; it++) {
        const int flat = tid + (it << 7);
        const int m  = flat >> 4;
        const int jj = flat & 15;
        const int gm = m0 + m;
        const float* gi = g_GI + ((size_t)gm * Ssz + t) * G3 + j0 + jj;
        pgr[it] = gi[0];
        pgz[it] = gi[Hsz];
        pgn[it] = gi[2 * Hsz];
        php[it] = hprev[(size_t)gm * Hsz + j0 + jj];
    }

    // ldmatrix per-lane address components
    const int lrow = lane & 7;
    const int tsel = lane >> 3;                       // 0..3
    const int arow = ((tsel & 1) << 3) + lrow;        // A row within m16 tile
    const int akof = (tsel >> 1) << 3;                // A k offset (0/8 elems)
    const int brow = lrow;                            // B row within n8 tile
    const int bkof = ((lane >> 3) & 1) << 3;          // B k offset (0/8 elems)

    // split accumulators: accH = Ah*B, accL = Al*B
    float accH[3][4], accL[3][4];
#pragma unroll
    for (int j = 0; j < 3; j++)
#pragma unroll
        for (int e = 0; e < 4; e++) { accH[j][e] = 0.f; accL[j][e] = 0.f; }

    // ---- chunk loader (cp.async): A 32x32 fp16 (hi+lo), B 48x32 fp16
    auto load_chunk = [&](int c, int s) {
        const uint32_t sb = sb0 + (uint32_t)s * STAGE_B;
        const int k0 = c * KC;
        {
            const int row = tid >> 2, seg = tid & 3;   // 32 rows x 4 segs
            const size_t src = (size_t)(m0 + row) * Hsz + k0 + seg * 8;
            const uint32_t dst = sb + row * AROWB + seg * 16;
            cpasync16(dst + OFF_AH, hhin + src);
            cpasync16(dst + OFF_AL, hlin + src);
        }
#pragma unroll
        for (int i = 0; i < 2; i++) {
            const int task = tid + (i << 7);           // 0..255
            if (task < 192) {
                const int row = task >> 2, seg = task & 3;   // 48 rows x 4 segs
                const int gate = row >> 4, jj = row & 15;
                const size_t src = ((size_t)gate * Hsz + j0 + jj) * Hsz + k0 + seg * 8;
                cpasync16(sb + OFF_B + row * AROWB + seg * 16, g_wq + src);
            }
        }
        CP_COMMIT();
    };

    // prologue: 3 chunks in flight
#pragma unroll
    for (int c = 0; c < NSTAGE - 1; c++) load_chunk(c, c);

    for (int c = 0; c < NCH; c++) {
        const int s = c & (NSTAGE - 1);
        const int rem = NCH - 1 - c;
        if      (rem >= 2) CP_WAIT(2);
        else if (rem == 1) CP_WAIT(1);
        else               CP_WAIT(0);
        __syncthreads();   // publishes chunk c; proves compute c-1 done

        if (c + NSTAGE - 1 < NCH)
            load_chunk(c + NSTAGE - 1, (c + NSTAGE - 1) & (NSTAGE - 1));

        const uint32_t sb = sb0 + (uint32_t)s * STAGE_B;
        const uint32_t aH = sb + OFF_AH + (m0w + arow) * AROWB + akof * 2;
        const uint32_t aL = sb + OFF_AL + (m0w + arow) * AROWB + akof * 2;
        const uint32_t bB = sb + OFF_B  + (n0w + brow) * AROWB + bkof * 2;

#pragma unroll
        for (int ks = 0; ks < KC; ks += 16) {
            uint32_t Ah[4], Al[4], Bq[3][2];
            ldsm4(Ah, aH + ks * 2);
            ldsm4(Al, aL + ks * 2);
#pragma unroll
            for (int j = 0; j < 3; j++)
                ldsm2(Bq[j], bB + j * (8 * AROWB) + ks * 2);
#pragma unroll
            for (int j = 0; j < 3; j++) {
                mma_f16(accH[j], Ah, Bq[j]);
                mma_f16(accL[j], Al, Bq[j]);
            }
        }
        // no trailing barrier: next iteration's top barrier protects stage reuse
    }
    __syncthreads();   // all compute done before reusing smem for epilogue

    // ---- dump gh = accH + accL to smem, padded stride
    float* ghs = reinterpret_cast<float*>(dsmem);
    const int crow = m0w + (lane >> 2);
    const int ccol = n0w + ((lane & 3) << 1);
#pragma unroll
    for (int j = 0; j < 3; j++) {
        const int col = ccol + (j << 3);
        *reinterpret_cast<float2*>(&ghs[crow * GH_STR + col]) =
            make_float2(accH[j][0] + accL[j][0], accH[j][1] + accL[j][1]);
        *reinterpret_cast<float2*>(&ghs[(crow + 8) * GH_STR + col]) =
            make_float2(accH[j][2] + accL[j][2], accH[j][3] + accL[j][3]);
    }
    __syncthreads();

    // ---- GRU gates: 512 (m, jj) pairs, 4 per thread (operands prefetched)
#pragma unroll
    for (int it = 0; it < 4; it++) {
        const int flat = tid + (it << 7);
        const int m  = flat >> 4;
        const int jj = flat & 15;
        const int j  = j0 + jj;
        const int gm = m0 + m;

        const float ghr = ghs[m * GH_STR + jj]       + bhh[j];
        const float ghz = ghs[m * GH_STR + 16 + jj]  + bhh[Hsz + j];
        const float ghn = ghs[m * GH_STR + 32 + jj]  + bhh[2 * Hsz + j];

        const float r  = sigf(pgr[it] + ghr);
        const float z  = sigf(pgz[it] + ghz);
        const float nn = tanhf(pgn[it] + r * ghn);
        const float hv = (1.f - z) * nn + z * php[it];

        hout[(size_t)gm * Hsz + j] = hv;
        const __half hi = __float2half_rn(hv);
        hhout[(size_t)gm * Hsz + j] = hi;
        hlout[(size_t)gm * Hsz + j] = __float2half_rn(hv - __half2float(hi));
    }
}

// ---------------------------------------------------------------------------
// Quantize Whh to fp16, once per run
__global__ void quant_whh_kernel(const float* __restrict__ Whh)
{
    const size_t idx = (size_t)blockIdx.x * blockDim.x + threadIdx.x;
    g_wq[idx] = __float2half_rn(Whh[idx]);
}

__global__ void zero_h_kernel()
{
    const int idx = blockIdx.x * blockDim.x + threadIdx.x;
    g_hbuf[0][idx] = 0.f;
    g_hh[0][idx] = __float2half(0.f);
    g_hl[0][idx] = __float2half(0.f);
}

// ---------------------------------------------------------------------------
// Generic tiled SGEMM with bias (parallel GEMMs: GI, G2, GH, projector)
// ---------------------------------------------------------------------------
__global__ __launch_bounds__(256) void sgemm_bias(
    const float* __restrict__ A, int lda,
    const float* __restrict__ W,
    const float* __restrict__ bias,
    float* __restrict__ C,
    int N, int K)
{
    __shared__ float As[16][64];
    __shared__ float Bsh[16][64];

    const int tid  = threadIdx.x;
    const int tx   = tid & 15;
    const int ty   = tid >> 4;
    const int row0 = blockIdx.y << 6;
    const int col0 = blockIdx.x << 6;

    const int lm = tid >> 2;
    const int lk = (tid & 3) << 2;

    float acc[4][4] = {};

    for (int k0 = 0; k0 < K; k0 += 16) {
#pragma unroll
        for (int c = 0; c < 4; c++) {
            const int k = k0 + lk + c;
            As[lk + c][lm] = (k < K) ? A[(size_t)(row0 + lm) * lda + k] : 0.f;
            const int n = col0 + lm;
            Bsh[lk + c][lm] = (k < K && n < N) ? W[(size_t)n * K + k] : 0.f;
        }
        __syncthreads();

#pragma unroll
        for (int k = 0; k < 16; k++) {
            const float4 av = *reinterpret_cast<const float4*>(&As[k][ty << 2]);
            const float4 bv = *reinterpret_cast<const float4*>(&Bsh[k][tx << 2]);
            const float a[4] = {av.x, av.y, av.z, av.w};
            const float b[4] = {bv.x, bv.y, bv.z, bv.w};
#pragma unroll
            for (int i = 0; i < 4; i++)
#pragma unroll
                for (int j = 0; j < 4; j++)
                    acc[i][j] = fmaf(a[i], b[j], acc[i][j]);
        }
        __syncthreads();
    }

#pragma unroll
    for (int i = 0; i < 4; i++) {
        const int m = row0 + (ty << 2) + i;
#pragma unroll
        for (int j = 0; j < 4; j++) {
            const int n = col0 + (tx << 2) + j;
            if (n < N)
                C[(size_t)m * N + n] = acc[i][j] + bias[n];
        }
    }
}

// Decoder gates: every timestep uses the same enc_h and the same gh row.
__global__ void gates_dec_kernel(const float* __restrict__ hfin)
{
    const size_t idx = (size_t)blockIdx.x * blockDim.x + threadIdx.x;
    const int j  = (int)(idx & (Hsz - 1));
    const int bt = (int)(idx >> 10);
    const int b  = bt >> 6;
    const float* gi = g_G2 + (size_t)bt * G3;
    const float* gh = g_GH + (size_t)b * G3;

    const float r  = sigf(gi[j]          + gh[j]);
    const float z  = sigf(gi[Hsz + j]    + gh[Hsz + j]);
    const float nn = tanhf(gi[2*Hsz + j] + r * gh[2*Hsz + j]);
    const float hp = hfin[(size_t)b * Hsz + j];
    g_states[idx] = (1.f - z) * nn + z * hp;
}

// ---------------------------------------------------------------------------
extern "C" void kernel_launch(void* const* d_in, const int* in_sizes, int n_in,
                              void* d_out, int out_size)
{
    const float* enc_in  = (const float*)d_in[0];
    const float* dec_in  = (const float*)d_in[1];
    const float* enc_Wih = (const float*)d_in[2];
    const float* enc_Whh = (const float*)d_in[3];
    const float* enc_bih = (const float*)d_in[4];
    const float* enc_bhh = (const float*)d_in[5];
    const float* dec_Wih = (const float*)d_in[6];
    const float* dec_Whh = (const float*)d_in[7];
    const float* dec_bih = (const float*)d_in[8];
    const float* dec_bhh = (const float*)d_in[9];
    const float* proj_W  = (const float*)d_in[10];
    const float* proj_b  = (const float*)d_in[11];
    float* out = (float*)d_out;

    float *GI, *G2, *GH, *states, *hbuf;
    __half *hh, *hl;
    cudaGetSymbolAddress((void**)&GI,     g_GI);
    cudaGetSymbolAddress((void**)&G2,     g_G2);
    cudaGetSymbolAddress((void**)&GH,     g_GH);
    cudaGetSymbolAddress((void**)&states, g_states);
    cudaGetSymbolAddress((void**)&hbuf,   g_hbuf);
    cudaGetSymbolAddress((void**)&hh,     g_hh);
    cudaGetSymbolAddress((void**)&hl,     g_hl);
    float* hf0 = hbuf;
    float* hf1 = hbuf + (size_t)Bsz * Hsz;
    __half* hh0 = hh; __half* hh1 = hh + (size_t)Bsz * Hsz;
    __half* hl0 = hl; __half* hl1 = hl + (size_t)Bsz * Hsz;

    const dim3 blk256(256);

    zero_h_kernel<<<(Bsz * Hsz) / 256, blk256>>>();
    quant_whh_kernel<<<(int)(((size_t)G3 * Hsz) / 256), blk256>>>(enc_Whh);

    // Encoder input gates for ALL timesteps
    sgemm_bias<<<dim3(G3 / 64, (Bsz * Ssz) / 64), blk256>>>(
        enc_in, Isz, enc_Wih, enc_bih, GI, G3, Isz);

    // Encoder recurrence: 128 sequential fp16 2-MMA steps
    for (int t = 0; t < Ssz; t++) {
        const int s = t & 1;
        gru_step_f16<<<dim3(Hsz / 16, Bsz / 32), 128, DSMEM>>>(
            s ? hh1 : hh0, s ? hl1 : hl0, s ? hf1 : hf0,
            s ? hf0 : hf1, s ? hh0 : hh1, s ? hl0 : hl1,
            enc_bhh, t);
    }
    float* enc_h = hf0;   // 128 steps (even) -> buffer 0

    // Decoder hidden-side gates (shared by all T timesteps)
    sgemm_bias<<<dim3(G3 / 64, Bsz / 64), blk256>>>(
        enc_h, Hsz, dec_Whh, dec_bhh, GH, G3, Hsz);

    // Decoder input-side gates for all timesteps
    sgemm_bias<<<dim3(G3 / 64, (Bsz * Tsz) / 64), blk256>>>(
        dec_in, Isz, dec_Wih, dec_bih, G2, G3, Isz);

    // Decoder gates -> states (B*T, H)
    gates_dec_kernel<<<(int)(((size_t)Bsz * Tsz * Hsz) / 256), blk256>>>(enc_h);

    // Projector: out (B*T, I) = states @ proj_W^T + proj_b
    sgemm_bias<<<dim3((Isz + 63) / 64, (Bsz * Tsz) / 64), blk256>>>(
        states, Hsz, proj_W, proj_b, out, Isz, Hsz);
}

// round 13
// speedup vs baseline: 2.2715x; 1.2616x over previous
#include <cuda_runtime.h>
#include <cuda_fp16.h>
#include <math.h>
#include <stdint.h>

// Problem dims
#define Bsz 256
#define Ssz 128
#define Tsz 64
#define Isz 63
#define Hsz 1024
#define G3  (3*Hsz)   // 3072

// Scratch (device globals — no allocations allowed)
__device__ float g_GI[(size_t)Bsz * Ssz * G3];      // encoder gi_all (B*S, 3H)
__device__ float g_G2[(size_t)Bsz * Tsz * G3];      // decoder gi     (B*T, 3H)
__device__ float g_GH[(size_t)Bsz * G3];            // decoder gh     (B, 3H)
__device__ float g_states[(size_t)Bsz * Tsz * Hsz]; // decoder states (B*T, H)
__device__ float g_hbuf[2][(size_t)Bsz * Hsz];      // hidden fp32, double buffered
__device__ __half g_hh[2][(size_t)Bsz * Hsz];       // h fp16 (single digit)
__device__ __half g_wq[(size_t)G3 * Hsz];           // Whh quantized fp16

// ---------------------------------------------------------------------------
__device__ __forceinline__ uint32_t smem_u32(const void* p) {
    uint32_t a;
    asm("{ .reg .u64 t; cvta.to.shared.u64 t, %1; cvt.u32.u64 %0, t; }"
        : "=r"(a) : "l"(p));
    return a;
}
__device__ __forceinline__ void cpasync16(uint32_t dst, const void* src) {
    asm volatile("cp.async.cg.shared.global [%0], [%1], 16;"
                 :: "r"(dst), "l"(src) : "memory");
}
#define CP_COMMIT() asm volatile("cp.async.commit_group;" ::: "memory")
#define CP_WAIT(n)  asm volatile("cp.async.wait_group %0;" :: "n"(n) : "memory")

__device__ __forceinline__ void ldsm4(uint32_t* r, uint32_t addr) {
    asm volatile("ldmatrix.sync.aligned.m8n8.x4.shared.b16 {%0,%1,%2,%3}, [%4];"
                 : "=r"(r[0]), "=r"(r[1]), "=r"(r[2]), "=r"(r[3]) : "r"(addr));
}
__device__ __forceinline__ void ldsm2(uint32_t* r, uint32_t addr) {
    asm volatile("ldmatrix.sync.aligned.m8n8.x2.shared.b16 {%0,%1}, [%2];"
                 : "=r"(r[0]), "=r"(r[1]) : "r"(addr));
}
__device__ __forceinline__ void mma_f16(float* d, const uint32_t* a, const uint32_t* b) {
    asm volatile("mma.sync.aligned.m16n8k16.row.col.f32.f16.f16.f32 "
                 "{%0,%1,%2,%3}, {%4,%5,%6,%7}, {%8,%9}, {%0,%1,%2,%3};"
                 : "+f"(d[0]), "+f"(d[1]), "+f"(d[2]), "+f"(d[3])
                 : "r"(a[0]), "r"(a[1]), "r"(a[2]), "r"(a[3]),
                   "r"(b[0]), "r"(b[1]));
}

__device__ __forceinline__ float sigf(float x) { return 1.f / (1.f + expf(-x)); }

// ---------------------------------------------------------------------------
// fp16 single-MMA warp-MMA fused GRU step.
// gh = A*B with A=fp16(h), B=fp16(w); fp32 h kept separately for the update.
// CTA tile M=32, N=48 (16 j x 3 gates), K=1024 in 16 chunks of 64.
// Grid (64 j, 8 m) = 512 CTAs; 128 threads = 4 warps as 2m x 2n (warp 16x24).
// Per chunk per warp: 4x (1 ldsm4 + 3 ldsm2 + 3 mma).
// 4-stage cp.async pipeline (stage 11.25KB, 45KB total <48KB).
// Rows padded to 144B: 8 rows span all 8 distinct 16B groups mod 128 ->
// conflict-free ldmatrix.
// ---------------------------------------------------------------------------
#define KC 64                  // k-elements per chunk
#define NCH (Hsz / KC)         // 16
#define NSTAGE 4
#define AROWB 144              // 64 fp16 = 128B + 16B pad
#define OFF_A  0u
#define OFF_B  4608u           // 32*144
#define STAGE_B 11520u         // + 48*144
#define DSMEM (NSTAGE * 11520) // 46080 (<48KB)
#define GH_STR 52

__global__ __launch_bounds__(128) void gru_step_f16(
    const __half* __restrict__ hhin,
    const float* __restrict__ hprev,
    float*       __restrict__ hout,
    __half* __restrict__ hhout,
    const float* __restrict__ bhh,
    int t)
{
    extern __shared__ __align__(16) char dsmem[];
    const uint32_t sb0 = smem_u32(dsmem);

    const int tid  = threadIdx.x;
    const int wid  = tid >> 5;
    const int lane = tid & 31;
    const int j0   = blockIdx.x << 4;     // 16 j per CTA
    const int m0   = blockIdx.y << 5;     // 32 batch per CTA

    const int wm  = wid & 1;              // 2 m-warps (16 rows each)
    const int wn  = wid >> 1;             // 2 n-warps (24 cols each)
    const int m0w = wm << 4;
    const int n0w = wn * 24;

    // ---- epilogue operand prefetch (DRAM latency hidden behind mainloop)
    float pgr[4], pgz[4], pgn[4], php[4];
#pragma unroll
    for (int it = 0; it < 4; it++) {
        const int flat = tid + (it << 7);
        const int m  = flat >> 4;
        const int jj = flat & 15;
        const int gm = m0 + m;
        const float* gi = g_GI + ((size_t)gm * Ssz + t) * G3 + j0 + jj;
        pgr[it] = gi[0];
        pgz[it] = gi[Hsz];
        pgn[it] = gi[2 * Hsz];
        php[it] = hprev[(size_t)gm * Hsz + j0 + jj];
    }

    // ldmatrix per-lane address components
    const int lrow = lane & 7;
    const int tsel = lane >> 3;                       // 0..3
    const int arow = ((tsel & 1) << 3) + lrow;        // A row within m16 tile
    const int akof = (tsel >> 1) << 3;                // A k offset (0/8 elems)
    const int brow = lrow;                            // B row within n8 tile
    const int bkof = ((lane >> 3) & 1) << 3;          // B k offset (0/8 elems)

    float acc[3][4];
#pragma unroll
    for (int j = 0; j < 3; j++)
#pragma unroll
        for (int e = 0; e < 4; e++) acc[j][e] = 0.f;

    // ---- chunk loader (cp.async): A 32x64 fp16, B 48x64 fp16
    auto load_chunk = [&](int c, int s) {
        const uint32_t sb = sb0 + (uint32_t)s * STAGE_B;
        const int k0 = c * KC;
#pragma unroll
        for (int i = 0; i < 2; i++) {
            const int task = tid + (i << 7);          // 0..255 (32 rows x 8 segs)
            const int row = task >> 3, seg = task & 7;
            const size_t src = (size_t)(m0 + row) * Hsz + k0 + seg * 8;
            cpasync16(sb + OFF_A + row * AROWB + seg * 16, hhin + src);
        }
#pragma unroll
        for (int i = 0; i < 3; i++) {
            const int task = tid + (i << 7);          // 0..383 (48 rows x 8 segs)
            const int row = task >> 3, seg = task & 7;
            const int gate = row >> 4, jj = row & 15;
            const size_t src = ((size_t)gate * Hsz + j0 + jj) * Hsz + k0 + seg * 8;
            cpasync16(sb + OFF_B + row * AROWB + seg * 16, g_wq + src);
        }
        CP_COMMIT();
    };

    // prologue: 3 chunks in flight
#pragma unroll
    for (int c = 0; c < NSTAGE - 1; c++) load_chunk(c, c);

    for (int c = 0; c < NCH; c++) {
        const int s = c & (NSTAGE - 1);
        const int rem = NCH - 1 - c;
        if      (rem >= 2) CP_WAIT(2);
        else if (rem == 1) CP_WAIT(1);
        else               CP_WAIT(0);
        __syncthreads();   // publishes chunk c; proves compute c-1 done

        if (c + NSTAGE - 1 < NCH)
            load_chunk(c + NSTAGE - 1, (c + NSTAGE - 1) & (NSTAGE - 1));

        const uint32_t sb = sb0 + (uint32_t)s * STAGE_B;
        const uint32_t aA = sb + OFF_A + (m0w + arow) * AROWB + akof * 2;
        const uint32_t bB = sb + OFF_B + (n0w + brow) * AROWB + bkof * 2;

#pragma unroll
        for (int ks = 0; ks < KC; ks += 16) {
            uint32_t Aq[4], Bq[3][2];
            ldsm4(Aq, aA + ks * 2);
#pragma unroll
            for (int j = 0; j < 3; j++)
                ldsm2(Bq[j], bB + j * (8 * AROWB) + ks * 2);
#pragma unroll
            for (int j = 0; j < 3; j++)
                mma_f16(acc[j], Aq, Bq[j]);
        }
        // no trailing barrier: next iteration's top barrier protects stage reuse
    }
    __syncthreads();   // all compute done before reusing smem for epilogue

    // ---- dump gh to smem, padded stride
    float* ghs = reinterpret_cast<float*>(dsmem);
    const int crow = m0w + (lane >> 2);
    const int ccol = n0w + ((lane & 3) << 1);
#pragma unroll
    for (int j = 0; j < 3; j++) {
        const int col = ccol + (j << 3);
        *reinterpret_cast<float2*>(&ghs[crow * GH_STR + col]) =
            make_float2(acc[j][0], acc[j][1]);
        *reinterpret_cast<float2*>(&ghs[(crow + 8) * GH_STR + col]) =
            make_float2(acc[j][2], acc[j][3]);
    }
    __syncthreads();

    // ---- GRU gates: 512 (m, jj) pairs, 4 per thread (operands prefetched)
#pragma unroll
    for (int it = 0; it < 4; it++) {
        const int flat = tid + (it << 7);
        const int m  = flat >> 4;
        const int jj = flat & 15;
        const int j  = j0 + jj;
        const int gm = m0 + m;

        const float ghr = ghs[m * GH_STR + jj]       + bhh[j];
        const float ghz = ghs[m * GH_STR + 16 + jj]  + bhh[Hsz + j];
        const float ghn = ghs[m * GH_STR + 32 + jj]  + bhh[2 * Hsz + j];

        const float r  = sigf(pgr[it] + ghr);
        const float z  = sigf(pgz[it] + ghz);
        const float nn = tanhf(pgn[it] + r * ghn);
        const float hv = (1.f - z) * nn + z * php[it];

        hout[(size_t)gm * Hsz + j] = hv;
        hhout[(size_t)gm * Hsz + j] = __float2half_rn(hv);
    }
}

// ---------------------------------------------------------------------------
// Quantize Whh to fp16, once per run
__global__ void quant_whh_kernel(const float* __restrict__ Whh)
{
    const size_t idx = (size_t)blockIdx.x * blockDim.x + threadIdx.x;
    g_wq[idx] = __float2half_rn(Whh[idx]);
}

__global__ void zero_h_kernel()
{
    const int idx = blockIdx.x * blockDim.x + threadIdx.x;
    g_hbuf[0][idx] = 0.f;
    g_hh[0][idx] = __float2half(0.f);
}

// ---------------------------------------------------------------------------
// Generic tiled SGEMM with bias (parallel GEMMs: GI, G2, GH, projector)
// ---------------------------------------------------------------------------
__global__ __launch_bounds__(256) void sgemm_bias(
    const float* __restrict__ A, int lda,
    const float* __restrict__ W,
    const float* __restrict__ bias,
    float* __restrict__ C,
    int N, int K)
{
    __shared__ float As[16][64];
    __shared__ float Bsh[16][64];

    const int tid  = threadIdx.x;
    const int tx   = tid & 15;
    const int ty   = tid >> 4;
    const int row0 = blockIdx.y << 6;
    const int col0 = blockIdx.x << 6;

    const int lm = tid >> 2;
    const int lk = (tid & 3) << 2;

    float acc[4][4] = {};

    for (int k0 = 0; k0 < K; k0 += 16) {
#pragma unroll
        for (int c = 0; c < 4; c++) {
            const int k = k0 + lk + c;
            As[lk + c][lm] = (k < K) ? A[(size_t)(row0 + lm) * lda + k] : 0.f;
            const int n = col0 + lm;
            Bsh[lk + c][lm] = (k < K && n < N) ? W[(size_t)n * K + k] : 0.f;
        }
        __syncthreads();

#pragma unroll
        for (int k = 0; k < 16; k++) {
            const float4 av = *reinterpret_cast<const float4*>(&As[k][ty << 2]);
            const float4 bv = *reinterpret_cast<const float4*>(&Bsh[k][tx << 2]);
            const float a[4] = {av.x, av.y, av.z, av.w};
            const float b[4] = {bv.x, bv.y, bv.z, bv.w};
#pragma unroll
            for (int i = 0; i < 4; i++)
#pragma unroll
                for (int j = 0; j < 4; j++)
                    acc[i][j] = fmaf(a[i], b[j], acc[i][j]);
        }
        __syncthreads();
    }

#pragma unroll
    for (int i = 0; i < 4; i++) {
        const int m = row0 + (ty << 2) + i;
#pragma unroll
        for (int j = 0; j < 4; j++) {
            const int n = col0 + (tx << 2) + j;
            if (n < N)
                C[(size_t)m * N + n] = acc[i][j] + bias[n];
        }
    }
}

// Decoder gates: every timestep uses the same enc_h and the same gh row.
__global__ void gates_dec_kernel(const float* __restrict__ hfin)
{
    const size_t idx = (size_t)blockIdx.x * blockDim.x + threadIdx.x;
    const int j  = (int)(idx & (Hsz - 1));
    const int bt = (int)(idx >> 10);
    const int b  = bt >> 6;
    const float* gi = g_G2 + (size_t)bt * G3;
    const float* gh = g_GH + (size_t)b * G3;

    const float r  = sigf(gi[j]          + gh[j]);
    const float z  = sigf(gi[Hsz + j]    + gh[Hsz + j]);
    const float nn = tanhf(gi[2*Hsz + j] + r * gh[2*Hsz + j]);
    const float hp = hfin[(size_t)b * Hsz + j];
    g_states[idx] = (1.f - z) * nn + z * hp;
}

// ---------------------------------------------------------------------------
extern "C" void kernel_launch(void* const* d_in, const int* in_sizes, int n_in,
                              void* d_out, int out_size)
{
    const float* enc_in  = (const float*)d_in[0];
    const float* dec_in  = (const float*)d_in[1];
    const float* enc_Wih = (const float*)d_in[2];
    const float* enc_Whh = (const float*)d_in[3];
    const float* enc_bih = (const float*)d_in[4];
    const float* enc_bhh = (const float*)d_in[5];
    const float* dec_Wih = (const float*)d_in[6];
    const float* dec_Whh = (const float*)d_in[7];
    const float* dec_bih = (const float*)d_in[8];
    const float* dec_bhh = (const float*)d_in[9];
    const float* proj_W  = (const float*)d_in[10];
    const float* proj_b  = (const float*)d_in[11];
    float* out = (float*)d_out;

    float *GI, *G2, *GH, *states, *hbuf;
    __half *hh;
    cudaGetSymbolAddress((void**)&GI,     g_GI);
    cudaGetSymbolAddress((void**)&G2,     g_G2);
    cudaGetSymbolAddress((void**)&GH,     g_GH);
    cudaGetSymbolAddress((void**)&states, g_states);
    cudaGetSymbolAddress((void**)&hbuf,   g_hbuf);
    cudaGetSymbolAddress((void**)&hh,     g_hh);
    float* hf0 = hbuf;
    float* hf1 = hbuf + (size_t)Bsz * Hsz;
    __half* hh0 = hh; __half* hh1 = hh + (size_t)Bsz * Hsz;

    const dim3 blk256(256);

    zero_h_kernel<<<(Bsz * Hsz) / 256, blk256>>>();
    quant_whh_kernel<<<(int)(((size_t)G3 * Hsz) / 256), blk256>>>(enc_Whh);

    // Encoder input gates for ALL timesteps
    sgemm_bias<<<dim3(G3 / 64, (Bsz * Ssz) / 64), blk256>>>(
        enc_in, Isz, enc_Wih, enc_bih, GI, G3, Isz);

    // Encoder recurrence: 128 sequential fp16 1-MMA steps
    for (int t = 0; t < Ssz; t++) {
        const int s = t & 1;
        gru_step_f16<<<dim3(Hsz / 16, Bsz / 32), 128, DSMEM>>>(
            s ? hh1 : hh0, s ? hf1 : hf0,
            s ? hf0 : hf1, s ? hh0 : hh1,
            enc_bhh, t);
    }
    float* enc_h = hf0;   // 128 steps (even) -> buffer 0

    // Decoder hidden-side gates (shared by all T timesteps)
    sgemm_bias<<<dim3(G3 / 64, Bsz / 64), blk256>>>(
        enc_h, Hsz, dec_Whh, dec_bhh, GH, G3, Hsz);

    // Decoder input-side gates for all timesteps
    sgemm_bias<<<dim3(G3 / 64, (Bsz * Tsz) / 64), blk256>>>(
        dec_in, Isz, dec_Wih, dec_bih, G2, G3, Isz);

    // Decoder gates -> states (B*T, H)
    gates_dec_kernel<<<(int)(((size_t)Bsz * Tsz * Hsz) / 256), blk256>>>(enc_h);

    // Projector: out (B*T, I) = states @ proj_W^T + proj_b
    sgemm_bias<<<dim3((Isz + 63) / 64, (Bsz * Tsz) / 64), blk256>>>(
        states, Hsz, proj_W, proj_b, out, Isz, Hsz);
}

// round 14
// speedup vs baseline: 2.7980x; 1.2318x over previous
#include <cuda_runtime.h>
#include <cuda_fp16.h>
#include <math.h>
#include <stdint.h>

// Problem dims
#define Bsz 256
#define Ssz 128
#define Tsz 64
#define Isz 63
#define Hsz 1024
#define G3  (3*Hsz)   // 3072
#define KP  64        // padded input dim

// Scratch (device globals — no allocations allowed)
__device__ __half g_GIh[(size_t)Bsz * Ssz * G3];    // encoder gi_all fp16
__device__ __half g_G2h[(size_t)Bsz * Tsz * G3];    // decoder gi fp16
__device__ float g_GH[(size_t)Bsz * G3];            // decoder gh (B, 3H)
__device__ float g_states[(size_t)Bsz * Tsz * Hsz]; // decoder states (B*T, H)
__device__ float g_hbuf[2][(size_t)Bsz * Hsz];      // hidden fp32, double buffered
__device__ __half g_hh[2][(size_t)Bsz * Hsz];       // h fp16
__device__ __half g_wq[(size_t)G3 * Hsz];           // enc Whh fp16
__device__ __half g_encin_h[(size_t)Bsz * Ssz * KP];// enc inputs fp16, padded K=64
__device__ __half g_decin_h[(size_t)Bsz * Tsz * KP];// dec inputs fp16, padded
__device__ __half g_wih1_h[(size_t)G3 * KP];        // enc Wih fp16, padded
__device__ __half g_wih2_h[(size_t)G3 * KP];        // dec Wih fp16, padded

// ---------------------------------------------------------------------------
__device__ __forceinline__ uint32_t smem_u32(const void* p) {
    uint32_t a;
    asm("{ .reg .u64 t; cvta.to.shared.u64 t, %1; cvt.u32.u64 %0, t; }"
        : "=r"(a) : "l"(p));
    return a;
}
__device__ __forceinline__ void cpasync16(uint32_t dst, const void* src) {
    asm volatile("cp.async.cg.shared.global [%0], [%1], 16;"
                 :: "r"(dst), "l"(src) : "memory");
}
#define CP_COMMIT() asm volatile("cp.async.commit_group;" ::: "memory")
#define CP_WAIT(n)  asm volatile("cp.async.wait_group %0;" :: "n"(n) : "memory")

__device__ __forceinline__ void ldsm4(uint32_t* r, uint32_t addr) {
    asm volatile("ldmatrix.sync.aligned.m8n8.x4.shared.b16 {%0,%1,%2,%3}, [%4];"
                 : "=r"(r[0]), "=r"(r[1]), "=r"(r[2]), "=r"(r[3]) : "r"(addr));
}
__device__ __forceinline__ void ldsm2(uint32_t* r, uint32_t addr) {
    asm volatile("ldmatrix.sync.aligned.m8n8.x2.shared.b16 {%0,%1}, [%2];"
                 : "=r"(r[0]), "=r"(r[1]) : "r"(addr));
}
__device__ __forceinline__ void mma_f16(float* d, const uint32_t* a, const uint32_t* b) {
    asm volatile("mma.sync.aligned.m16n8k16.row.col.f32.f16.f16.f32 "
                 "{%0,%1,%2,%3}, {%4,%5,%6,%7}, {%8,%9}, {%0,%1,%2,%3};"
                 : "+f"(d[0]), "+f"(d[1]), "+f"(d[2]), "+f"(d[3])
                 : "r"(a[0]), "r"(a[1]), "r"(a[2]), "r"(a[3]),
                   "r"(b[0]), "r"(b[1]));
}

__device__ __forceinline__ float sigf(float x) { return 1.f / (1.f + expf(-x)); }

// ---------------------------------------------------------------------------
// fp16 single-MMA warp-MMA fused GRU step (unchanged from R13 except gi fp16).
// CTA tile M=32, N=48 (16 j x 3 gates), K=1024 in 16 chunks of 64.
// Grid (64 j, 8 m) = 512 CTAs; 128 threads = 4 warps as 2m x 2n.
// ---------------------------------------------------------------------------
#define KC 64
#define NCH (Hsz / KC)         // 16
#define NSTAGE 4
#define AROWB 144
#define OFF_A  0u
#define OFF_B  4608u           // 32*144
#define STAGE_B 11520u         // + 48*144
#define DSMEM (NSTAGE * 11520) // 46080
#define GH_STR 52

__global__ __launch_bounds__(128) void gru_step_f16(
    const __half* __restrict__ hhin,
    const float* __restrict__ hprev,
    float*       __restrict__ hout,
    __half* __restrict__ hhout,
    const float* __restrict__ bhh,
    int t)
{
    extern __shared__ __align__(16) char dsmem[];
    const uint32_t sb0 = smem_u32(dsmem);

    const int tid  = threadIdx.x;
    const int wid  = tid >> 5;
    const int lane = tid & 31;
    const int j0   = blockIdx.x << 4;
    const int m0   = blockIdx.y << 5;

    const int wm  = wid & 1;
    const int wn  = wid >> 1;
    const int m0w = wm << 4;
    const int n0w = wn * 24;

    // ---- epilogue operand prefetch (gi now fp16)
    float pgr[4], pgz[4], pgn[4], php[4];
#pragma unroll
    for (int it = 0; it < 4; it++) {
        const int flat = tid + (it << 7);
        const int m  = flat >> 4;
        const int jj = flat & 15;
        const int gm = m0 + m;
        const __half* gi = g_GIh + ((size_t)gm * Ssz + t) * G3 + j0 + jj;
        pgr[it] = __half2float(gi[0]);
        pgz[it] = __half2float(gi[Hsz]);
        pgn[it] = __half2float(gi[2 * Hsz]);
        php[it] = hprev[(size_t)gm * Hsz + j0 + jj];
    }

    const int lrow = lane & 7;
    const int tsel = lane >> 3;
    const int arow = ((tsel & 1) << 3) + lrow;
    const int akof = (tsel >> 1) << 3;
    const int brow = lrow;
    const int bkof = ((lane >> 3) & 1) << 3;

    float acc[3][4];
#pragma unroll
    for (int j = 0; j < 3; j++)
#pragma unroll
        for (int e = 0; e < 4; e++) acc[j][e] = 0.f;

    auto load_chunk = [&](int c, int s) {
        const uint32_t sb = sb0 + (uint32_t)s * STAGE_B;
        const int k0 = c * KC;
#pragma unroll
        for (int i = 0; i < 2; i++) {
            const int task = tid + (i << 7);
            const int row = task >> 3, seg = task & 7;
            const size_t src = (size_t)(m0 + row) * Hsz + k0 + seg * 8;
            cpasync16(sb + OFF_A + row * AROWB + seg * 16, hhin + src);
        }
#pragma unroll
        for (int i = 0; i < 3; i++) {
            const int task = tid + (i << 7);
            const int row = task >> 3, seg = task & 7;
            const int gate = row >> 4, jj = row & 15;
            const size_t src = ((size_t)gate * Hsz + j0 + jj) * Hsz + k0 + seg * 8;
            cpasync16(sb + OFF_B + row * AROWB + seg * 16, g_wq + src);
        }
        CP_COMMIT();
    };

#pragma unroll
    for (int c = 0; c < NSTAGE - 1; c++) load_chunk(c, c);

    for (int c = 0; c < NCH; c++) {
        const int s = c & (NSTAGE - 1);
        const int rem = NCH - 1 - c;
        if      (rem >= 2) CP_WAIT(2);
        else if (rem == 1) CP_WAIT(1);
        else               CP_WAIT(0);
        __syncthreads();

        if (c + NSTAGE - 1 < NCH)
            load_chunk(c + NSTAGE - 1, (c + NSTAGE - 1) & (NSTAGE - 1));

        const uint32_t sb = sb0 + (uint32_t)s * STAGE_B;
        const uint32_t aA = sb + OFF_A + (m0w + arow) * AROWB + akof * 2;
        const uint32_t bB = sb + OFF_B + (n0w + brow) * AROWB + bkof * 2;

#pragma unroll
        for (int ks = 0; ks < KC; ks += 16) {
            uint32_t Aq[4], Bq[3][2];
            ldsm4(Aq, aA + ks * 2);
#pragma unroll
            for (int j = 0; j < 3; j++)
                ldsm2(Bq[j], bB + j * (8 * AROWB) + ks * 2);
#pragma unroll
            for (int j = 0; j < 3; j++)
                mma_f16(acc[j], Aq, Bq[j]);
        }
    }
    __syncthreads();

    float* ghs = reinterpret_cast<float*>(dsmem);
    const int crow = m0w + (lane >> 2);
    const int ccol = n0w + ((lane & 3) << 1);
#pragma unroll
    for (int j = 0; j < 3; j++) {
        const int col = ccol + (j << 3);
        *reinterpret_cast<float2*>(&ghs[crow * GH_STR + col]) =
            make_float2(acc[j][0], acc[j][1]);
        *reinterpret_cast<float2*>(&ghs[(crow + 8) * GH_STR + col]) =
            make_float2(acc[j][2], acc[j][3]);
    }
    __syncthreads();

#pragma unroll
    for (int it = 0; it < 4; it++) {
        const int flat = tid + (it << 7);
        const int m  = flat >> 4;
        const int jj = flat & 15;
        const int j  = j0 + jj;
        const int gm = m0 + m;

        const float ghr = ghs[m * GH_STR + jj]       + bhh[j];
        const float ghz = ghs[m * GH_STR + 16 + jj]  + bhh[Hsz + j];
        const float ghn = ghs[m * GH_STR + 32 + jj]  + bhh[2 * Hsz + j];

        const float r  = sigf(pgr[it] + ghr);
        const float z  = sigf(pgz[it] + ghz);
        const float nn = tanhf(pgn[it] + r * ghn);
        const float hv = (1.f - z) * nn + z * php[it];

        hout[(size_t)gm * Hsz + j] = hv;
        hhout[(size_t)gm * Hsz + j] = __float2half_rn(hv);
    }
}

// ---------------------------------------------------------------------------
// fp16 tensor GEMM for the input-gate GEMMs (K=64 single chunk):
// C[r][n] = fp16( bias[n] + sum_k A[r][k] * W[n][k] ),  N = 3072 fixed.
// CTA tile M=64, N=64; 256 threads = 8 warps as 4m x 2n (warp 16x32).
// ---------------------------------------------------------------------------
#define GM_AROWB 144

__global__ __launch_bounds__(256) void gemm_f16_k64(
    const __half* __restrict__ A,     // (rows, 64) padded
    const __half* __restrict__ W,     // (3072, 64) padded
    const float*  __restrict__ bias,  // (3072)
    __half* __restrict__ C)           // (rows, 3072)
{
    __shared__ __align__(16) char sm[2 * 64 * GM_AROWB];   // A then B, 18.4KB
    const uint32_t smA = smem_u32(sm);
    const uint32_t smB = smA + 64 * GM_AROWB;

    const int tid  = threadIdx.x;
    const int wid  = tid >> 5;
    const int lane = tid & 31;
    const int col0 = blockIdx.x << 6;
    const int row0 = blockIdx.y << 6;

    const int wm  = wid & 3;             // 4 m-warps (16 rows)
    const int wn  = wid >> 2;            // 2 n-warps (32 cols)
    const int m0w = wm << 4;
    const int n0w = wn << 5;

    // loads: A 64x64 fp16 = 64 rows x 8 segs; B same
#pragma unroll
    for (int i = 0; i < 2; i++) {
        const int task = tid + (i << 8);            // 0..511
        const int row = task >> 3, seg = task & 7;
        cpasync16(smA + row * GM_AROWB + seg * 16,
                  A + (size_t)(row0 + row) * KP + seg * 8);
        cpasync16(smB + row * GM_AROWB + seg * 16,
                  W + (size_t)(col0 + row) * KP + seg * 8);
    }
    CP_COMMIT();

    const int lrow = lane & 7;
    const int tsel = lane >> 3;
    const int arow = ((tsel & 1) << 3) + lrow;
    const int akof = (tsel >> 1) << 3;
    const int brow = lrow;
    const int bkof = ((tsel & 1) << 3);

    float acc[4][4];
#pragma unroll
    for (int j = 0; j < 4; j++)
#pragma unroll
        for (int e = 0; e < 4; e++) acc[j][e] = 0.f;

    CP_WAIT(0);
    __syncthreads();

    const uint32_t aA = smA + (m0w + arow) * GM_AROWB + akof * 2;
    const uint32_t bB = smB + (n0w + brow) * GM_AROWB + bkof * 2;

#pragma unroll
    for (int ks = 0; ks < KP; ks += 16) {
        uint32_t Aq[4], Bq[4][2];
        ldsm4(Aq, aA + ks * 2);
#pragma unroll
        for (int j = 0; j < 4; j++)
            ldsm2(Bq[j], bB + j * (8 * GM_AROWB) + ks * 2);
#pragma unroll
        for (int j = 0; j < 4; j++)
            mma_f16(acc[j], Aq, Bq[j]);
    }

    // epilogue: add bias, store fp16 (half2 per fragment pair)
    const int crow = row0 + m0w + (lane >> 2);
    const int ccol0 = col0 + n0w + ((lane & 3) << 1);
#pragma unroll
    for (int j = 0; j < 4; j++) {
        const int col = ccol0 + (j << 3);
        const float b0 = bias[col], b1 = bias[col + 1];
        __half2 v0, v1;
        v0.x = __float2half_rn(acc[j][0] + b0);
        v0.y = __float2half_rn(acc[j][1] + b1);
        v1.x = __float2half_rn(acc[j][2] + b0);
        v1.y = __float2half_rn(acc[j][3] + b1);
        *reinterpret_cast<__half2*>(&C[(size_t)crow * G3 + col]) = v0;
        *reinterpret_cast<__half2*>(&C[(size_t)(crow + 8) * G3 + col]) = v1;
    }
}

// ---------------------------------------------------------------------------
// Quantize helpers
__global__ void quant_whh_kernel(const float* __restrict__ Whh)
{
    const size_t idx = (size_t)blockIdx.x * blockDim.x + threadIdx.x;
    g_wq[idx] = __float2half_rn(Whh[idx]);
}

// pad 63 -> 64 fp16
__global__ void quant_pad63_kernel(const float* __restrict__ src,
                                   __half* __restrict__ dst)
{
    const size_t idx = (size_t)blockIdx.x * blockDim.x + threadIdx.x;
    const size_t row = idx >> 6;
    const int c = (int)(idx & 63);
    dst[idx] = (c < Isz) ? __float2half_rn(src[row * Isz + c]) : __half(0);
}

__global__ void zero_h_kernel()
{
    const int idx = blockIdx.x * blockDim.x + threadIdx.x;
    g_hbuf[0][idx] = 0.f;
    g_hh[0][idx] = __half(0);
}

// ---------------------------------------------------------------------------
// fp32 SGEMM with bias (kept for GH and projector)
__global__ __launch_bounds__(256) void sgemm_bias(
    const float* __restrict__ A, int lda,
    const float* __restrict__ W,
    const float* __restrict__ bias,
    float* __restrict__ C,
    int N, int K)
{
    __shared__ float As[16][64];
    __shared__ float Bsh[16][64];

    const int tid  = threadIdx.x;
    const int tx   = tid & 15;
    const int ty   = tid >> 4;
    const int row0 = blockIdx.y << 6;
    const int col0 = blockIdx.x << 6;

    const int lm = tid >> 2;
    const int lk = (tid & 3) << 2;

    float acc[4][4] = {};

    for (int k0 = 0; k0 < K; k0 += 16) {
#pragma unroll
        for (int c = 0; c < 4; c++) {
            const int k = k0 + lk + c;
            As[lk + c][lm] = (k < K) ? A[(size_t)(row0 + lm) * lda + k] : 0.f;
            const int n = col0 + lm;
            Bsh[lk + c][lm] = (k < K && n < N) ? W[(size_t)n * K + k] : 0.f;
        }
        __syncthreads();

#pragma unroll
        for (int k = 0; k < 16; k++) {
            const float4 av = *reinterpret_cast<const float4*>(&As[k][ty << 2]);
            const float4 bv = *reinterpret_cast<const float4*>(&Bsh[k][tx << 2]);
            const float a[4] = {av.x, av.y, av.z, av.w};
            const float b[4] = {bv.x, bv.y, bv.z, bv.w};
#pragma unroll
            for (int i = 0; i < 4; i++)
#pragma unroll
                for (int j = 0; j < 4; j++)
                    acc[i][j] = fmaf(a[i], b[j], acc[i][j]);
        }
        __syncthreads();
    }

#pragma unroll
    for (int i = 0; i < 4; i++) {
        const int m = row0 + (ty << 2) + i;
#pragma unroll
        for (int j = 0; j < 4; j++) {
            const int n = col0 + (tx << 2) + j;
            if (n < N)
                C[(size_t)m * N + n] = acc[i][j] + bias[n];
        }
    }
}

// Decoder gates (reads fp16 gi)
__global__ void gates_dec_kernel(const float* __restrict__ hfin)
{
    const size_t idx = (size_t)blockIdx.x * blockDim.x + threadIdx.x;
    const int j  = (int)(idx & (Hsz - 1));
    const int bt = (int)(idx >> 10);
    const int b  = bt >> 6;
    const __half* gi = g_G2h + (size_t)bt * G3;
    const float* gh = g_GH + (size_t)b * G3;

    const float r  = sigf(__half2float(gi[j])          + gh[j]);
    const float z  = sigf(__half2float(gi[Hsz + j])    + gh[Hsz + j]);
    const float nn = tanhf(__half2float(gi[2*Hsz + j]) + r * gh[2*Hsz + j]);
    const float hp = hfin[(size_t)b * Hsz + j];
    g_states[idx] = (1.f - z) * nn + z * hp;
}

// ---------------------------------------------------------------------------
extern "C" void kernel_launch(void* const* d_in, const int* in_sizes, int n_in,
                              void* d_out, int out_size)
{
    const float* enc_in  = (const float*)d_in[0];
    const float* dec_in  = (const float*)d_in[1];
    const float* enc_Wih = (const float*)d_in[2];
    const float* enc_Whh = (const float*)d_in[3];
    const float* enc_bih = (const float*)d_in[4];
    const float* enc_bhh = (const float*)d_in[5];
    const float* dec_Wih = (const float*)d_in[6];
    const float* dec_Whh = (const float*)d_in[7];
    const float* dec_bih = (const float*)d_in[8];
    const float* dec_bhh = (const float*)d_in[9];
    const float* proj_W  = (const float*)d_in[10];
    const float* proj_b  = (const float*)d_in[11];
    float* out = (float*)d_out;

    cudaFuncSetAttribute(gru_step_f16,
                         cudaFuncAttributeMaxDynamicSharedMemorySize, DSMEM);

    float *GH, *states, *hbuf;
    __half *GIh, *G2h, *hh, *encin, *decin, *wih1, *wih2;
    cudaGetSymbolAddress((void**)&GIh,    g_GIh);
    cudaGetSymbolAddress((void**)&G2h,    g_G2h);
    cudaGetSymbolAddress((void**)&GH,     g_GH);
    cudaGetSymbolAddress((void**)&states, g_states);
    cudaGetSymbolAddress((void**)&hbuf,   g_hbuf);
    cudaGetSymbolAddress((void**)&hh,     g_hh);
    cudaGetSymbolAddress((void**)&encin,  g_encin_h);
    cudaGetSymbolAddress((void**)&decin,  g_decin_h);
    cudaGetSymbolAddress((void**)&wih1,   g_wih1_h);
    cudaGetSymbolAddress((void**)&wih2,   g_wih2_h);
    float* hf0 = hbuf;
    float* hf1 = hbuf + (size_t)Bsz * Hsz;
    __half* hh0 = hh; __half* hh1 = hh + (size_t)Bsz * Hsz;

    const dim3 blk256(256);

    zero_h_kernel<<<(Bsz * Hsz) / 256, blk256>>>();
    quant_whh_kernel<<<(int)(((size_t)G3 * Hsz) / 256), blk256>>>(enc_Whh);
    quant_pad63_kernel<<<(int)(((size_t)Bsz * Ssz * KP) / 256), blk256>>>(enc_in, encin);
    quant_pad63_kernel<<<(int)(((size_t)Bsz * Tsz * KP) / 256), blk256>>>(dec_in, decin);
    quant_pad63_kernel<<<(int)(((size_t)G3 * KP) / 256), blk256>>>(enc_Wih, wih1);
    quant_pad63_kernel<<<(int)(((size_t)G3 * KP) / 256), blk256>>>(dec_Wih, wih2);

    // Encoder input gates (fp16 tensor GEMM): GI = enc_in @ Wih^T + bih
    gemm_f16_k64<<<dim3(G3 / 64, (Bsz * Ssz) / 64), blk256>>>(
        encin, wih1, enc_bih, GIh);

    // Encoder recurrence: 128 sequential fp16 1-MMA steps
    for (int t = 0; t < Ssz; t++) {
        const int s = t & 1;
        gru_step_f16<<<dim3(Hsz / 16, Bsz / 32), 128, DSMEM>>>(
            s ? hh1 : hh0, s ? hf1 : hf0,
            s ? hf0 : hf1, s ? hh0 : hh1,
            enc_bhh, t);
    }
    float* enc_h = hf0;   // 128 steps (even) -> buffer 0

    // Decoder hidden-side gates (fp32, small)
    sgemm_bias<<<dim3(G3 / 64, Bsz / 64), blk256>>>(
        enc_h, Hsz, dec_Whh, dec_bhh, GH, G3, Hsz);

    // Decoder input-side gates (fp16 tensor GEMM)
    gemm_f16_k64<<<dim3(G3 / 64, (Bsz * Tsz) / 64), blk256>>>(
        decin, wih2, dec_bih, G2h);

    // Decoder gates -> states (B*T, H)
    gates_dec_kernel<<<(int)(((size_t)Bsz * Tsz * Hsz) / 256), blk256>>>(enc_h);

    // Projector: out (B*T, I) = states @ proj_W^T + proj_b  (fp32)
    sgemm_bias<<<dim3((Isz + 63) / 64, (Bsz * Tsz) / 64), blk256>>>(
        states, Hsz, proj_W, proj_b, out, Isz, Hsz);
}